// round 16
// baseline (speedup 1.0000x reference)
#include <cuda_runtime.h>

// ---------------------------------------------------------------------------
// ImprovedAILayerNorm: int8-quantized layernorm with LUT integer sqrt.
// R16 = R14 (best: PDL chain, serpentine, v8 evict_last reductions, MLP=4
// quant) + software-pipelined reduction passes: 8 rows per block, next row's
// LDG.256 issued BEFORE the current row's reduce/barrier/leader tail, so the
// load stream never drains. Per-row smem buffers -> 1 barrier per row.
// ---------------------------------------------------------------------------

#define T2 512
#define T3 256
#define RPB 8
#define NWARP (T2 / 32)
#define MAX_ROWS 32768

__device__ int   g_absmax_bits;
__device__ int   g_ymax_bits;
__device__ int   g_const_flag;
__device__ float g_g0, g_b0;
__device__ float g_mu[MAX_ROWS];
__device__ float g_inv_std[MAX_ROWS];
__device__ float g_rowmin[MAX_ROWS];
__device__ float g_rowmax[MAX_ROWS];

__device__ __forceinline__ void pdl_launch_dependents() {
    asm volatile("griddepcontrol.launch_dependents;" ::: "memory");
}
__device__ __forceinline__ void pdl_wait() {
    asm volatile("griddepcontrol.wait;" ::: "memory");
}

struct F8 { float v[8]; };

// 256-bit load, L2 evict_last (keep x resident across passes)
__device__ __forceinline__ F8 ldg_keep8(const float* p) {
    unsigned u0, u1, u2, u3, u4, u5, u6, u7;
    asm volatile(
        "ld.global.L2::evict_last.v8.b32 {%0,%1,%2,%3,%4,%5,%6,%7}, [%8];"
        : "=r"(u0), "=r"(u1), "=r"(u2), "=r"(u3),
          "=r"(u4), "=r"(u5), "=r"(u6), "=r"(u7)
        : "l"(p));
    F8 r;
    r.v[0] = __uint_as_float(u0); r.v[1] = __uint_as_float(u1);
    r.v[2] = __uint_as_float(u2); r.v[3] = __uint_as_float(u3);
    r.v[4] = __uint_as_float(u4); r.v[5] = __uint_as_float(u5);
    r.v[6] = __uint_as_float(u6); r.v[7] = __uint_as_float(u7);
    return r;
}

// ---------------------------------------------------------------------------
__global__ void k_init_check(const float* __restrict__ gamma,
                             const float* __restrict__ beta, int N) {
    pdl_launch_dependents();
    if (threadIdx.x == 0) {
        g_absmax_bits = 0;
        g_ymax_bits   = 0;
        g_const_flag  = 1;
        g_g0 = gamma[0];
        g_b0 = beta[0];
    }
    __syncthreads();
    float g0 = g_g0, b0 = g_b0;
    bool bad = false;
    for (int i = threadIdx.x; i < N; i += blockDim.x)
        bad |= (gamma[i] != g0) || (beta[i] != b0);
    if (__syncthreads_or(bad) && threadIdx.x == 0) g_const_flag = 0;
}

// ordered-uint mapping for float min/max redux
__device__ __forceinline__ unsigned f2ord(float f) {
    unsigned u = __float_as_uint(f);
    return (u & 0x80000000u) ? ~u : (u | 0x80000000u);
}
__device__ __forceinline__ float ord2f(unsigned u) {
    return __uint_as_float((u & 0x80000000u) ? (u & 0x7fffffffu) : ~u);
}

// ---------------------------------------------------------------------------
// Pass 1: 8 rows/block, pipelined. ASCENDING rows.
__global__ void __launch_bounds__(T2)
k_minmax(const float* __restrict__ x, int N) {
    pdl_launch_dependents();
    const int r0 = blockIdx.x * RPB;
    const float* base = x + (size_t)r0 * N + threadIdx.x * 8;
    const int w = threadIdx.x >> 5;

    __shared__ unsigned smn[RPB][NWARP], smx[RPB][NWARP];

    F8 cur = ldg_keep8(base);
    float blk_am = 0.0f;                 // leader-tracked block absmax

    #pragma unroll
    for (int i = 0; i < RPB; i++) {
        F8 nxt;
        if (i + 1 < RPB) nxt = ldg_keep8(base + (size_t)(i + 1) * N);

        float mn = cur.v[0], mx = cur.v[0];
        #pragma unroll
        for (int c = 1; c < 8; c++) {
            mn = fminf(mn, cur.v[c]);
            mx = fmaxf(mx, cur.v[c]);
        }
        unsigned wmn = __reduce_min_sync(0xffffffffu, f2ord(mn));
        unsigned wmx = __reduce_max_sync(0xffffffffu, f2ord(mx));
        if ((threadIdx.x & 31) == 0) { smn[i][w] = wmn; smx[i][w] = wmx; }
        __syncthreads();
        if (threadIdx.x == 0) {
            unsigned umn = smn[i][0], umx = smx[i][0];
            #pragma unroll
            for (int j = 1; j < NWARP; j++) {
                umn = min(umn, smn[i][j]);
                umx = max(umx, smx[i][j]);
            }
            float fmn = ord2f(umn), fmx = ord2f(umx);
            g_rowmin[r0 + i] = fmn;
            g_rowmax[r0 + i] = fmx;
            blk_am = fmaxf(blk_am, fmaxf(fabsf(fmn), fabsf(fmx)));
        }
        cur = nxt;
    }
    if (threadIdx.x == 0) {
        pdl_wait();                          // init's zeroing visible
        atomicMax(&g_absmax_bits, (int)__float_as_uint(blk_am));
    }
}

// ---------------------------------------------------------------------------
// Exact replica of reference sqrt_rounded_vec (LUT-based rounded int sqrt)
__device__ __forceinline__ float sqrt_rounded(int d) {
    int msb = 31 - __clz(d);
    int k   = msb >> 1;
    int dn  = d << ((7 - k) * 2);
    int addr = (dn >> 8) & 255;
    int v    = addr * 256 + 128;
    int mant = (int)sqrtf((float)v);
    if (mant * mant > v) mant--;
    if ((mant + 1) * (mant + 1) <= v) mant++;
    int qf = mant >> (7 - k);
    int boundary = qf * qf + qf;
    return (float)((d > boundary) ? qf + 1 : qf);
}

// ---------------------------------------------------------------------------
// Pass 2: 8 rows/block, pipelined, DESCENDING block order. No clamps
// (|x|/s <= 127 by construction of s).
__global__ void __launch_bounds__(T2)
k_rowstats(const float* __restrict__ x,
           const float* __restrict__ gamma,
           const float* __restrict__ beta,
           int N, int rows) {
    pdl_launch_dependents();
    const int r0 = rows - RPB - blockIdx.x * RPB;        // descending groups
    const float* base = x + (size_t)r0 * N + threadIdx.x * 8;
    const int w = threadIdx.x >> 5;

    __shared__ int ssum[RPB][NWARP], ssum2[RPB][NWARP];

    F8 cur = ldg_keep8(base);                             // pre-wait preload
    pdl_wait();                                           // absmax/flag final
    const bool cst = (g_const_flag != 0);
    const float s     = fmaxf(__int_as_float(g_absmax_bits) / 127.0f, 1e-8f);
    const float inv_s = 1.0f / s;
    unsigned blk_ymax = 0u;                               // leader-tracked

    #pragma unroll
    for (int i = 0; i < RPB; i++) {
        F8 nxt;
        if (i + 1 < RPB) nxt = ldg_keep8(base + (size_t)(i + 1) * N);

        int su = 0, su2 = 0;
        #pragma unroll
        for (int c = 0; c < 8; c++) {
            int q = __float2int_rn(cur.v[c] * inv_s);     // RN half-even
            su  += q;
            su2 += q * q;
        }
        su  = __reduce_add_sync(0xffffffffu, su);
        su2 = __reduce_add_sync(0xffffffffu, su2);
        if ((threadIdx.x & 31) == 0) { ssum[i][w] = su; ssum2[i][w] = su2; }
        __syncthreads();
        if (threadIdx.x == 0) {
            int t = 0, t2 = 0;
            #pragma unroll
            for (int j = 0; j < NWARP; j++) { t += ssum[i][j]; t2 += ssum2[i][j]; }
            const int row = r0 + i;
            float Ex  = (float)t  * s;
            float Ex2 = (float)t2 * (s * s);
            float mu  = Ex / (float)N;
            float var = fmaxf(Ex2 / (float)N - mu * mu, 0.0f);
            float vi  = fminf(fmaxf(rintf(var), 1.0f), 65535.0f);
            float inv = 1.0f / fmaxf(sqrt_rounded((int)vi), 1e-5f);
            g_mu[row] = mu;
            g_inv_std[row] = inv;
            if (cst) {
                float g0 = g_g0, b0 = g_b0;
                float y1 = fabsf((g_rowmax[row] - mu) * inv * g0 + b0);
                float y2 = fabsf((g_rowmin[row] - mu) * inv * g0 + b0);
                blk_ymax = max(blk_ymax,
                               __float_as_uint(fmaxf(y1, y2)));
            }
        }
        cur = nxt;
    }
    if (cst) {
        if (threadIdx.x == 0) atomicMax(&g_ymax_bits, (int)blk_ymax);
        return;
    }

    // ---- general gamma/beta path: re-sweep the 8 rows for max|y| ----
    __syncthreads();                       // g_mu/g_inv_std visible in block
    const float4* g4 = reinterpret_cast<const float4*>(gamma);
    const float4* b4 = reinterpret_cast<const float4*>(beta);
    float ymax = 0.0f;
    for (int i = 0; i < RPB; i++) {
        const int row = r0 + i;
        const float mu = g_mu[row];
        const float is = g_inv_std[row];
        const float4* xr = reinterpret_cast<const float4*>(x + (size_t)row * N);
        for (int j = threadIdx.x; j < N / 4; j += T2) {
            float4 v = xr[j];
            float4 g = g4[j];
            float4 b = b4[j];
            #pragma unroll
            for (int c = 0; c < 4; c++) {
                float y = ((&v.x)[c] - mu) * is * (&g.x)[c] + (&b.x)[c];
                ymax = fmaxf(ymax, fabsf(y));
            }
        }
    }
    unsigned yb = __reduce_max_sync(0xffffffffu, __float_as_uint(ymax));
    __shared__ unsigned sy[NWARP];
    if ((threadIdx.x & 31) == 0) sy[w] = yb;
    __syncthreads();
    if (threadIdx.x == 0) {
        unsigned v = 0;
        #pragma unroll
        for (int i = 0; i < NWARP; i++) v = max(v, sy[i]);
        atomicMax(&g_ymax_bits, (int)v);
    }
}

// ---------------------------------------------------------------------------
// Pass 3: 1 row/block, 256 thr, 4 independent __ldcs float4 loads (MLP=4).
// ASCENDING rows; out streamed with __stcs. (Unchanged from R14 — roofline.)
__global__ void __launch_bounds__(T3)
k_quant(const float* __restrict__ x,
        const float* __restrict__ gamma,
        const float* __restrict__ beta,
        float* __restrict__ out,
        int N) {
    const int row = blockIdx.x;
    const float4* xr = reinterpret_cast<const float4*>(x + (size_t)row * N);
    float4* orow = reinterpret_cast<float4*>(out + (size_t)row * N);

    float4 v0 = __ldcs(&xr[threadIdx.x]);
    float4 v1 = __ldcs(&xr[T3 + threadIdx.x]);
    float4 v2 = __ldcs(&xr[2 * T3 + threadIdx.x]);
    float4 v3 = __ldcs(&xr[3 * T3 + threadIdx.x]);

    pdl_wait();                                        // mu/inv_std/ymax final
    const float mu = g_mu[row];
    const float is = g_inv_std[row];
    const float so     = fmaxf(__int_as_float(g_ymax_bits) / 127.0f, 1e-8f);
    const float inv_so = 1.0f / so;

    if (g_const_flag) {
        const float g0 = g_g0, b0 = g_b0;
        const float A2 = is * g0 * inv_so;
        const float B2 = (b0 - mu * is * g0) * inv_so;
        float4 o0, o1, o2, o3;
        #pragma unroll
        for (int c = 0; c < 4; c++) {
            int q0 = __float2int_rn(fmaf((&v0.x)[c], A2, B2));
            int q1 = __float2int_rn(fmaf((&v1.x)[c], A2, B2));
            int q2 = __float2int_rn(fmaf((&v2.x)[c], A2, B2));
            int q3 = __float2int_rn(fmaf((&v3.x)[c], A2, B2));
            q0 = max(-127, min(127, q0));              // safety vs reassoc ulp
            q1 = max(-127, min(127, q1));
            q2 = max(-127, min(127, q2));
            q3 = max(-127, min(127, q3));
            (&o0.x)[c] = (float)q0 * so;
            (&o1.x)[c] = (float)q1 * so;
            (&o2.x)[c] = (float)q2 * so;
            (&o3.x)[c] = (float)q3 * so;
        }
        __stcs(&orow[threadIdx.x], o0);
        __stcs(&orow[T3 + threadIdx.x], o1);
        __stcs(&orow[2 * T3 + threadIdx.x], o2);
        __stcs(&orow[3 * T3 + threadIdx.x], o3);
        return;
    }

    const float4* g4 = reinterpret_cast<const float4*>(gamma);
    const float4* b4 = reinterpret_cast<const float4*>(beta);
    #pragma unroll
    for (int j = 0; j < 4; j++) {
        float4 v = (j == 0) ? v0 : (j == 1) ? v1 : (j == 2) ? v2 : v3;
        float4 g = g4[j * T3 + threadIdx.x];
        float4 b = b4[j * T3 + threadIdx.x];
        float4 o;
        #pragma unroll
        for (int c = 0; c < 4; c++) {
            float y = ((&v.x)[c] - mu) * is * (&g.x)[c] + (&b.x)[c];
            (&o.x)[c] = (float)__float2int_rn(y * inv_so) * so;
        }
        __stcs(&orow[j * T3 + threadIdx.x], o);
    }
}

// ---------------------------------------------------------------------------
static void launch_pdl(void* func, dim3 grid, dim3 block, void** args) {
    cudaLaunchConfig_t cfg = {};
    cfg.gridDim = grid;
    cfg.blockDim = block;
    cfg.stream = 0;
    cudaLaunchAttribute attr[1];
    attr[0].id = cudaLaunchAttributeProgrammaticStreamSerialization;
    attr[0].val.programmaticStreamSerializationAllowed = 1;
    cfg.attrs = attr;
    cfg.numAttrs = 1;
    cudaLaunchKernelExC(&cfg, func, args);
}

extern "C" void kernel_launch(void* const* d_in, const int* in_sizes, int n_in,
                              void* d_out, int out_size) {
    const float* x     = (const float*)d_in[0];
    const float* gamma = (const float*)d_in[1];
    const float* beta  = (const float*)d_in[2];
    float* out = (float*)d_out;

    int N    = in_sizes[1];              // 4096
    const int n = in_sizes[0];           // 4*2048*4096
    int rows = n / N;                    // 8192

    {   // init+check (plain launch)
        void* args[] = {(void*)&gamma, (void*)&beta, (void*)&N};
        cudaLaunchConfig_t cfg = {};
        cfg.gridDim = dim3(1); cfg.blockDim = dim3(T2); cfg.stream = 0;
        cudaLaunchKernelExC(&cfg, (void*)k_init_check, args);
    }
    {   // pass 1 (PDL after init)
        void* args[] = {(void*)&x, (void*)&N};
        launch_pdl((void*)k_minmax, dim3(rows / RPB), dim3(T2), args);
    }
    {   // pass 2 (PDL after pass 1)
        void* args[] = {(void*)&x, (void*)&gamma, (void*)&beta,
                        (void*)&N, (void*)&rows};
        launch_pdl((void*)k_rowstats, dim3(rows / RPB), dim3(T2), args);
    }
    {   // pass 3 (PDL after pass 2)
        void* args[] = {(void*)&x, (void*)&gamma, (void*)&beta,
                        (void*)&out, (void*)&N};
        launch_pdl((void*)k_quant, dim3(rows), dim3(T3), args);
    }
}

// round 17
// speedup vs baseline: 1.0858x; 1.0858x over previous
#include <cuda_runtime.h>

// ---------------------------------------------------------------------------
// ImprovedAILayerNorm: int8-quantized layernorm with LUT integer sqrt.
// R17 = R14 exactly (best, 87.4us: PDL chain, serpentine, 512thr/2row v8
// evict_last reductions, 256thr/MLP4 quant) + __launch_bounds__(256,6) on
// k_quant to cap regs at 40 and raise occupancy (41% -> ~60%).
// ---------------------------------------------------------------------------

#define T2 512
#define T3 256
#define NWARP (T2 / 32)
#define MAX_ROWS 32768

__device__ int   g_absmax_bits;
__device__ int   g_ymax_bits;
__device__ int   g_const_flag;
__device__ float g_g0, g_b0;
__device__ float g_mu[MAX_ROWS];
__device__ float g_inv_std[MAX_ROWS];
__device__ float g_rowmin[MAX_ROWS];
__device__ float g_rowmax[MAX_ROWS];

__device__ __forceinline__ void pdl_launch_dependents() {
    asm volatile("griddepcontrol.launch_dependents;" ::: "memory");
}
__device__ __forceinline__ void pdl_wait() {
    asm volatile("griddepcontrol.wait;" ::: "memory");
}

struct F8 { float v[8]; };

// 256-bit load, L2 evict_last (keep x resident across passes)
__device__ __forceinline__ F8 ldg_keep8(const float* p) {
    unsigned u0, u1, u2, u3, u4, u5, u6, u7;
    asm volatile(
        "ld.global.L2::evict_last.v8.b32 {%0,%1,%2,%3,%4,%5,%6,%7}, [%8];"
        : "=r"(u0), "=r"(u1), "=r"(u2), "=r"(u3),
          "=r"(u4), "=r"(u5), "=r"(u6), "=r"(u7)
        : "l"(p));
    F8 r;
    r.v[0] = __uint_as_float(u0); r.v[1] = __uint_as_float(u1);
    r.v[2] = __uint_as_float(u2); r.v[3] = __uint_as_float(u3);
    r.v[4] = __uint_as_float(u4); r.v[5] = __uint_as_float(u5);
    r.v[6] = __uint_as_float(u6); r.v[7] = __uint_as_float(u7);
    return r;
}

// ---------------------------------------------------------------------------
__global__ void k_init_check(const float* __restrict__ gamma,
                             const float* __restrict__ beta, int N) {
    pdl_launch_dependents();
    if (threadIdx.x == 0) {
        g_absmax_bits = 0;
        g_ymax_bits   = 0;
        g_const_flag  = 1;
        g_g0 = gamma[0];
        g_b0 = beta[0];
    }
    __syncthreads();
    float g0 = g_g0, b0 = g_b0;
    bool bad = false;
    for (int i = threadIdx.x; i < N; i += blockDim.x)
        bad |= (gamma[i] != g0) || (beta[i] != b0);
    if (__syncthreads_or(bad) && threadIdx.x == 0) g_const_flag = 0;
}

// ordered-uint mapping for float min/max redux
__device__ __forceinline__ unsigned f2ord(float f) {
    unsigned u = __float_as_uint(f);
    return (u & 0x80000000u) ? ~u : (u | 0x80000000u);
}
__device__ __forceinline__ float ord2f(unsigned u) {
    return __uint_as_float((u & 0x80000000u) ? (u & 0x7fffffffu) : ~u);
}

// ---------------------------------------------------------------------------
// Pass 1: 2 rows/block, row min/max + global absmax. ASCENDING rows.
__global__ void __launch_bounds__(T2)
k_minmax(const float* __restrict__ x, int N) {
    pdl_launch_dependents();
    const int r0 = blockIdx.x * 2;
    const float* xa = x + (size_t)r0 * N + threadIdx.x * 8;
    const float* xb = x + (size_t)(r0 + 1) * N + threadIdx.x * 8;

    F8 a = ldg_keep8(xa);
    F8 b = ldg_keep8(xb);

    float mnA = a.v[0], mxA = a.v[0];
    float mnB = b.v[0], mxB = b.v[0];
    #pragma unroll
    for (int c = 1; c < 8; c++) {
        mnA = fminf(mnA, a.v[c]); mxA = fmaxf(mxA, a.v[c]);
        mnB = fminf(mnB, b.v[c]); mxB = fmaxf(mxB, b.v[c]);
    }

    unsigned wmnA = __reduce_min_sync(0xffffffffu, f2ord(mnA));
    unsigned wmxA = __reduce_max_sync(0xffffffffu, f2ord(mxA));
    unsigned wmnB = __reduce_min_sync(0xffffffffu, f2ord(mnB));
    unsigned wmxB = __reduce_max_sync(0xffffffffu, f2ord(mxB));

    __shared__ unsigned smn[2][NWARP], smx[2][NWARP];
    const int w = threadIdx.x >> 5;
    if ((threadIdx.x & 31) == 0) {
        smn[0][w] = wmnA; smx[0][w] = wmxA;
        smn[1][w] = wmnB; smx[1][w] = wmxB;
    }
    __syncthreads();
    if (threadIdx.x == 0 || threadIdx.x == 32) {
        const int r = threadIdx.x >> 5;         // 0 or 1
        unsigned umn = 0xffffffffu, umx = 0u;
        #pragma unroll
        for (int i = 0; i < NWARP; i++) {
            umn = min(umn, smn[r][i]);
            umx = max(umx, smx[r][i]);
        }
        float fmn = ord2f(umn), fmx = ord2f(umx);
        g_rowmin[r0 + r] = fmn;
        g_rowmax[r0 + r] = fmx;
        float am = fmaxf(fabsf(fmn), fabsf(fmx));
        pdl_wait();                              // init's zeroing visible
        atomicMax(&g_absmax_bits, (int)__float_as_uint(am));
    }
}

// ---------------------------------------------------------------------------
// Exact replica of reference sqrt_rounded_vec (LUT-based rounded int sqrt)
__device__ __forceinline__ float sqrt_rounded(int d) {
    int msb = 31 - __clz(d);
    int k   = msb >> 1;
    int dn  = d << ((7 - k) * 2);
    int addr = (dn >> 8) & 255;
    int v    = addr * 256 + 128;
    int mant = (int)sqrtf((float)v);
    if (mant * mant > v) mant--;
    if ((mant + 1) * (mant + 1) <= v) mant++;
    int qf = mant >> (7 - k);
    int boundary = qf * qf + qf;
    return (float)((d > boundary) ? qf + 1 : qf);
}

__device__ __forceinline__ void row_finalize(int row, int t, int t2,
                                             float s, int N, bool cst) {
    float Ex  = (float)t  * s;
    float Ex2 = (float)t2 * (s * s);
    float mu  = Ex / (float)N;
    float var = fmaxf(Ex2 / (float)N - mu * mu, 0.0f);
    float vi  = fminf(fmaxf(rintf(var), 1.0f), 65535.0f);
    float inv = 1.0f / fmaxf(sqrt_rounded((int)vi), 1e-5f);
    g_mu[row] = mu;
    g_inv_std[row] = inv;
    if (cst) {
        float g0 = g_g0, b0 = g_b0;
        float y1 = fabsf((g_rowmax[row] - mu) * inv * g0 + b0);
        float y2 = fabsf((g_rowmin[row] - mu) * inv * g0 + b0);
        atomicMax(&g_ymax_bits, (int)__float_as_uint(fmaxf(y1, y2)));
    }
}

// ---------------------------------------------------------------------------
// Pass 2: 2 rows/block int moments, DESCENDING. No clamps
// (|x|/s <= 127 by construction of s). x preloaded (evict_last) pre-wait.
__global__ void __launch_bounds__(T2)
k_rowstats(const float* __restrict__ x,
           const float* __restrict__ gamma,
           const float* __restrict__ beta,
           int N, int rows) {
    pdl_launch_dependents();
    const int r0 = rows - 2 - blockIdx.x * 2;          // pair, descending
    const float* xa = x + (size_t)r0 * N + threadIdx.x * 8;
    const float* xb = x + (size_t)(r0 + 1) * N + threadIdx.x * 8;

    // preload x (independent of producer results), keep resident for pass 3
    F8 a = ldg_keep8(xa);
    F8 b = ldg_keep8(xb);

    pdl_wait();                                        // absmax/flag final
    const bool cst = (g_const_flag != 0);
    const float s     = fmaxf(__int_as_float(g_absmax_bits) / 127.0f, 1e-8f);
    const float inv_s = 1.0f / s;

    int sA = 0, s2A = 0, sB = 0, s2B = 0;
    #pragma unroll
    for (int c = 0; c < 8; c++) {
        int qa = __float2int_rn(a.v[c] * inv_s);       // RN half-even
        int qb = __float2int_rn(b.v[c] * inv_s);
        sA += qa;  s2A += qa * qa;
        sB += qb;  s2B += qb * qb;
    }
    sA  = __reduce_add_sync(0xffffffffu, sA);
    s2A = __reduce_add_sync(0xffffffffu, s2A);
    sB  = __reduce_add_sync(0xffffffffu, sB);
    s2B = __reduce_add_sync(0xffffffffu, s2B);

    __shared__ int sw[4][NWARP];
    const int w = threadIdx.x >> 5;
    if ((threadIdx.x & 31) == 0) {
        sw[0][w] = sA;  sw[1][w] = s2A;
        sw[2][w] = sB;  sw[3][w] = s2B;
    }
    __syncthreads();
    if (threadIdx.x == 0 || threadIdx.x == 32) {
        const int r = threadIdx.x >> 5;                // 0 or 1
        int t = 0, t2 = 0;
        #pragma unroll
        for (int i = 0; i < NWARP; i++) {
            t  += sw[2 * r][i];
            t2 += sw[2 * r + 1][i];
        }
        row_finalize(r0 + r, t, t2, s, N, cst);
    }
    if (cst) return;

    // ---- general gamma/beta path: sweep both rows for max|y| ----
    __syncthreads();
    const float* gp = gamma + threadIdx.x * 8;
    const float* bp = beta  + threadIdx.x * 8;
    float ymax = 0.0f;
    {
        const float muA = g_mu[r0],     isA = g_inv_std[r0];
        const float muB = g_mu[r0 + 1], isB = g_inv_std[r0 + 1];
        #pragma unroll
        for (int c = 0; c < 8; c++) {
            float gv = gp[c], bv = bp[c];
            float yA = (a.v[c] - muA) * isA * gv + bv;
            float yB = (b.v[c] - muB) * isB * gv + bv;
            ymax = fmaxf(ymax, fmaxf(fabsf(yA), fabsf(yB)));
        }
    }
    unsigned yb = __reduce_max_sync(0xffffffffu, __float_as_uint(ymax));
    __shared__ unsigned sy[NWARP];
    if ((threadIdx.x & 31) == 0) sy[w] = yb;
    __syncthreads();
    if (threadIdx.x == 0) {
        unsigned v = 0;
        #pragma unroll
        for (int i = 0; i < NWARP; i++) v = max(v, sy[i]);
        atomicMax(&g_ymax_bits, (int)v);
    }
}

// ---------------------------------------------------------------------------
// Pass 3: 1 row/block, 256 thr, 4 independent __ldcs float4 loads (MLP=4).
// ASCENDING rows; out streamed with __stcs. launch_bounds(256,6) caps regs
// at 40 for higher occupancy.
__global__ void __launch_bounds__(T3, 6)
k_quant(const float* __restrict__ x,
        const float* __restrict__ gamma,
        const float* __restrict__ beta,
        float* __restrict__ out,
        int N) {
    const int row = blockIdx.x;
    const float4* xr = reinterpret_cast<const float4*>(x + (size_t)row * N);
    float4* orow = reinterpret_cast<float4*>(out + (size_t)row * N);

    float4 v0 = __ldcs(&xr[threadIdx.x]);
    float4 v1 = __ldcs(&xr[T3 + threadIdx.x]);
    float4 v2 = __ldcs(&xr[2 * T3 + threadIdx.x]);
    float4 v3 = __ldcs(&xr[3 * T3 + threadIdx.x]);

    pdl_wait();                                        // mu/inv_std/ymax final
    const float mu = g_mu[row];
    const float is = g_inv_std[row];
    const float so     = fmaxf(__int_as_float(g_ymax_bits) / 127.0f, 1e-8f);
    const float inv_so = 1.0f / so;

    if (g_const_flag) {
        const float g0 = g_g0, b0 = g_b0;
        const float A2 = is * g0 * inv_so;
        const float B2 = (b0 - mu * is * g0) * inv_so;
        float4 o0, o1, o2, o3;
        #pragma unroll
        for (int c = 0; c < 4; c++) {
            int q0 = __float2int_rn(fmaf((&v0.x)[c], A2, B2));
            int q1 = __float2int_rn(fmaf((&v1.x)[c], A2, B2));
            int q2 = __float2int_rn(fmaf((&v2.x)[c], A2, B2));
            int q3 = __float2int_rn(fmaf((&v3.x)[c], A2, B2));
            q0 = max(-127, min(127, q0));              // safety vs reassoc ulp
            q1 = max(-127, min(127, q1));
            q2 = max(-127, min(127, q2));
            q3 = max(-127, min(127, q3));
            (&o0.x)[c] = (float)q0 * so;
            (&o1.x)[c] = (float)q1 * so;
            (&o2.x)[c] = (float)q2 * so;
            (&o3.x)[c] = (float)q3 * so;
        }
        __stcs(&orow[threadIdx.x], o0);
        __stcs(&orow[T3 + threadIdx.x], o1);
        __stcs(&orow[2 * T3 + threadIdx.x], o2);
        __stcs(&orow[3 * T3 + threadIdx.x], o3);
        return;
    }

    const float4* g4 = reinterpret_cast<const float4*>(gamma);
    const float4* b4 = reinterpret_cast<const float4*>(beta);
    #pragma unroll
    for (int j = 0; j < 4; j++) {
        float4 v = (j == 0) ? v0 : (j == 1) ? v1 : (j == 2) ? v2 : v3;
        float4 g = g4[j * T3 + threadIdx.x];
        float4 b = b4[j * T3 + threadIdx.x];
        float4 o;
        #pragma unroll
        for (int c = 0; c < 4; c++) {
            float y = ((&v.x)[c] - mu) * is * (&g.x)[c] + (&b.x)[c];
            (&o.x)[c] = (float)__float2int_rn(y * inv_so) * so;
        }
        __stcs(&orow[j * T3 + threadIdx.x], o);
    }
}

// ---------------------------------------------------------------------------
static void launch_pdl(void* func, dim3 grid, dim3 block, void** args) {
    cudaLaunchConfig_t cfg = {};
    cfg.gridDim = grid;
    cfg.blockDim = block;
    cfg.stream = 0;
    cudaLaunchAttribute attr[1];
    attr[0].id = cudaLaunchAttributeProgrammaticStreamSerialization;
    attr[0].val.programmaticStreamSerializationAllowed = 1;
    cfg.attrs = attr;
    cfg.numAttrs = 1;
    cudaLaunchKernelExC(&cfg, func, args);
}

extern "C" void kernel_launch(void* const* d_in, const int* in_sizes, int n_in,
                              void* d_out, int out_size) {
    const float* x     = (const float*)d_in[0];
    const float* gamma = (const float*)d_in[1];
    const float* beta  = (const float*)d_in[2];
    float* out = (float*)d_out;

    int N    = in_sizes[1];              // 4096
    const int n = in_sizes[0];           // 4*2048*4096
    int rows = n / N;                    // 8192

    {   // init+check (plain launch)
        void* args[] = {(void*)&gamma, (void*)&beta, (void*)&N};
        cudaLaunchConfig_t cfg = {};
        cfg.gridDim = dim3(1); cfg.blockDim = dim3(T2); cfg.stream = 0;
        cudaLaunchKernelExC(&cfg, (void*)k_init_check, args);
    }
    {   // pass 1 (PDL after init)
        void* args[] = {(void*)&x, (void*)&N};
        launch_pdl((void*)k_minmax, dim3(rows / 2), dim3(T2), args);
    }
    {   // pass 2 (PDL after pass 1)
        void* args[] = {(void*)&x, (void*)&gamma, (void*)&beta,
                        (void*)&N, (void*)&rows};
        launch_pdl((void*)k_rowstats, dim3(rows / 2), dim3(T2), args);
    }
    {   // pass 3 (PDL after pass 2)
        void* args[] = {(void*)&x, (void*)&gamma, (void*)&beta,
                        (void*)&out, (void*)&N};
        launch_pdl((void*)k_quant, dim3(rows), dim3(T3), args);
    }
}